// round 12
// baseline (speedup 1.0000x reference)
#include <cuda_runtime.h>
#include <cuda.h>
#include <cuda_bf16.h>
#include <cstdint>

#define BB 4
#define TT 2048
#define DD 1024
#define BT 8192
#define HDIM 64
#define MH 4096
#define N1 3072
#define N3 8192
#define LN_EPS 1e-6f
#define GN_EPS 1e-5f
#define RMS_EPS 1e-8f

__device__ float g_params[BB * 6 * DD];
__device__ float g_wpart[6 * 64];
__device__ float g_wsinv[6];
__device__ __align__(1024) __nv_bfloat16 g_WQ[16 * 1024 * 1024];  // wi|wf|wg|wo|gate(interleaved)|down
__device__ __align__(1024) __nv_bfloat16 g_Aq[BT * DD];
__device__ float g_rowscale[BT];
__device__ __align__(1024) __nv_bfloat16 g_HQ[(size_t)BT * MH];
__device__ float g_hscale[BT];
__device__ float g_L1[(size_t)BT * N1];
__device__ float g_H[(size_t)BT * DD];
__device__ float g_X2[(size_t)BT * DD];
__device__ float g_L3[(size_t)BT * N3];   // h = silu(gate)*y, [BT][MH]
__device__ float g_aggA[BB * 32 * DD];
__device__ float g_aggB[BB * 32 * DD];
__device__ float g_carry[BB * 32 * DD];

__device__ __forceinline__ float sigf(float x) { return 1.f / (1.f + expf(-x)); }
__device__ __forceinline__ float siluf(float x) { return x / (1.f + expf(-x)); }

__device__ __forceinline__ float bsum(float v, float* sm) {
#pragma unroll
    for (int o = 16; o; o >>= 1) v += __shfl_xor_sync(0xffffffffu, v, o);
    if ((threadIdx.x & 31) == 0) sm[threadIdx.x >> 5] = v;
    __syncthreads();
    v = sm[threadIdx.x & 7];
#pragma unroll
    for (int o = 4; o; o >>= 1) v += __shfl_xor_sync(0xffffffffu, v, o);
    return v;
}
__device__ __forceinline__ float bmax(float v, float* sm) {
#pragma unroll
    for (int o = 16; o; o >>= 1) v = fmaxf(v, __shfl_xor_sync(0xffffffffu, v, o));
    if ((threadIdx.x & 31) == 0) sm[threadIdx.x >> 5] = v;
    __syncthreads();
    v = sm[threadIdx.x & 7];
#pragma unroll
    for (int o = 4; o; o >>= 1) v = fmaxf(v, __shfl_xor_sync(0xffffffffu, v, o));
    return v;
}
__device__ __forceinline__ float qf(float t) {
    return fminf(fmaxf(rintf(t), -128.f), 127.f);
}

// ------------- fused: adaLN (blocks 0..3071) + weight |w| sums (3072..3455) --
__global__ void k_pre(const float* __restrict__ c, const float* __restrict__ w,
                      const float* __restrict__ bias,
                      const float* w0, const float* w1, const float* w2,
                      const float* w3, const float* w4, const float* w5) {
    __shared__ float sc[DD];
    int tid = threadIdx.x;
    if (blockIdx.x < 3072) {
        int b = blockIdx.x / 768, nb = blockIdx.x % 768;
        for (int k = tid; k < DD; k += 256) { float v = c[b * DD + k]; sc[k] = v / (1.f + expf(-v)); }
        __syncthreads();
        int wid = tid >> 5, l = tid & 31;
        int n = nb * 8 + wid;
        const float4* wr = (const float4*)(w + (size_t)n * DD);
        float s = 0.f;
        for (int k4 = l; k4 < 256; k4 += 32) {
            float4 v = wr[k4];
            s += v.x * sc[k4 * 4] + v.y * sc[k4 * 4 + 1] + v.z * sc[k4 * 4 + 2] + v.w * sc[k4 * 4 + 3];
        }
#pragma unroll
        for (int o = 16; o; o >>= 1) s += __shfl_xor_sync(0xffffffffu, s, o);
        if (l == 0) g_params[b * 6 * DD + n] = s + bias[n];
    } else {
        int bid = blockIdx.x - 3072;
        int mid = bid >> 6, part = bid & 63;
        const float* ww; int n;
        switch (mid) {
            case 0: ww = w0; n = DD * DD; break;
            case 1: ww = w1; n = DD * DD; break;
            case 2: ww = w2; n = DD * DD; break;
            case 3: ww = w3; n = DD * DD; break;
            case 4: ww = w4; n = N3 * DD; break;
            default: ww = w5; n = DD * MH; break;
        }
        float s = 0.f;
        for (int i = part * 256 + tid; i < n; i += 64 * 256) s += fabsf(ww[i]);
#pragma unroll
        for (int o = 16; o; o >>= 1) s += __shfl_xor_sync(0xffffffffu, s, o);
        if ((tid & 31) == 0) sc[tid >> 5] = s;
        __syncthreads();
        if (tid == 0) {
            float t = 0.f;
            for (int i = 0; i < 8; i++) t += sc[i];
            g_wpart[bid] = t;
        }
    }
}

// ------- LN + modulate + RMS + bf16-int quant; optional rider block = wfin ---
__global__ void k_lnmq(const float* __restrict__ xin, int shift_off, int scale_off) {
    __shared__ float red[4][8];
    int m = blockIdx.x, tid = threadIdx.x;
    if (m >= BT) {
        if (tid < 6) {
            float s = 0.f;
            for (int i = 0; i < 64; i++) s += g_wpart[tid * 64 + i];
            const float cnt[6] = {1048576.f, 1048576.f, 1048576.f, 1048576.f, 8388608.f, 4194304.f};
            g_wsinv[tid] = fmaxf(s / cnt[tid], 1e-5f);
        }
        return;
    }
    int b = m >> 11;
    float4 v = ((const float4*)(xin + (size_t)m * DD))[tid];
    float S1 = bsum(v.x + v.y + v.z + v.w, red[0]);
    float mu = S1 * (1.f / DD);
    float dx = v.x - mu, dy = v.y - mu, dz = v.z - mu, dw = v.w - mu;
    float S2 = bsum(dx * dx + dy * dy + dz * dz + dw * dw, red[1]);
    float rstd = rsqrtf(S2 * (1.f / DD) + LN_EPS);
    float4 sh = ((const float4*)(g_params + (size_t)b * 6 * DD + shift_off))[tid];
    float4 sc = ((const float4*)(g_params + (size_t)b * 6 * DD + scale_off))[tid];
    float4 mo;
    mo.x = dx * rstd * (1.f + sc.x) + sh.x;
    mo.y = dy * rstd * (1.f + sc.y) + sh.y;
    mo.z = dz * rstd * (1.f + sc.z) + sh.z;
    mo.w = dw * rstd * (1.f + sc.w) + sh.w;
    float Q2 = bsum(mo.x * mo.x + mo.y * mo.y + mo.z * mo.z + mo.w * mo.w, red[2]);
    float AM = bmax(fmaxf(fmaxf(fabsf(mo.x), fabsf(mo.y)), fmaxf(fabsf(mo.z), fabsf(mo.w))), red[3]);
    float rrms = rsqrtf(Q2 * (1.f / DD) + RMS_EPS);
    float clipm = fmaxf(AM * rrms, 1e-5f);
    if (tid == 0) g_rowscale[m] = clipm * (1.f / 127.f);
    float kk = rrms * 127.f / clipm;
    __nv_bfloat162* aq = (__nv_bfloat162*)(g_Aq + (size_t)m * DD);
    aq[tid * 2]     = __floats2bfloat162_rn(qf(mo.x * kk), qf(mo.y * kk));
    aq[tid * 2 + 1] = __floats2bfloat162_rn(qf(mo.z * kk), qf(mo.w * kk));
}

// ------- fused ternary weight quant (bf16 out); gate rows interleaved --------
__global__ void k_quantw_all(const float* __restrict__ wi, const float* __restrict__ wf,
                             const float* __restrict__ wg, const float* __restrict__ wo,
                             const float* __restrict__ gw, const float* __restrict__ dw) {
    int i4 = blockIdx.x * 256 + threadIdx.x;
    const float* src; int wsid; int rel;
    if (i4 < 262144)        { src = wi; wsid = 0; rel = i4; }
    else if (i4 < 524288)   { src = wf; wsid = 1; rel = i4 - 262144; }
    else if (i4 < 786432)   { src = wg; wsid = 2; rel = i4 - 524288; }
    else if (i4 < 1048576)  { src = wo; wsid = 3; rel = i4 - 786432; }
    else if (i4 < 3145728)  { src = gw; wsid = 4; rel = i4 - 1048576; }
    else                    { src = dw; wsid = 5; rel = i4 - 3145728; }
    float ws = 1.f / g_wsinv[wsid];
    float4 v = ((const float4*)src)[rel];
    float qx = fminf(fmaxf(rintf(v.x * ws), -1.f), 1.f);
    float qy = fminf(fmaxf(rintf(v.y * ws), -1.f), 1.f);
    float qz = fminf(fmaxf(rintf(v.z * ws), -1.f), 1.f);
    float qw = fminf(fmaxf(rintf(v.w * ws), -1.f), 1.f);
    int o4 = i4;
    if (wsid == 4) {
        int lr = rel >> 8, col4 = rel & 255;
        int nr = (lr < MH) ? (lr << 1) : (((lr - MH) << 1) | 1);
        o4 = 1048576 + (nr << 8) + col4;
    }
    __nv_bfloat162* dst = (__nv_bfloat162*)g_WQ;
    dst[o4 * 2]     = __floats2bfloat162_rn(qx, qy);
    dst[o4 * 2 + 1] = __floats2bfloat162_rn(qz, qw);
}

// ---------------- chunked scan (gate transform fused) ------------------------
__device__ __forceinline__ void gate_fi(float il, float fl, float& f, float& iv) {
    f = 1.f / (1.f + expf(-fl));
    iv = (il / (1.f + expf(-il))) * (1.f - f);
}
__global__ void k_scan1() {
    int u = blockIdx.x * 256 + threadIdx.x;
    int d = u & (DD - 1), cdx = (u >> 10) & 31, b = u >> 15;
    const float* base = g_L1 + (size_t)(b * TT + cdx * 64) * N1;
    float A = 1.f, Bv = 0.f;
#pragma unroll 4
    for (int t = 0; t < 64; t++) {
        float f, iv;
        gate_fi(base[(size_t)t * N1 + d], base[(size_t)t * N1 + DD + d], f, iv);
        A *= f;
        Bv = fmaf(Bv, f, iv);
    }
    int o = (b * 32 + cdx) * DD + d;
    g_aggA[o] = A; g_aggB[o] = Bv;
}
__global__ void k_scanc() {
    int v = blockIdx.x * 256 + threadIdx.x;
    int b = v >> 10, d = v & (DD - 1);
    float carry = 0.f;
    for (int cdx = 0; cdx < 32; cdx++) {
        int o = (b * 32 + cdx) * DD + d;
        g_carry[o] = carry;
        carry = fmaf(g_aggA[o], carry, g_aggB[o]);
    }
}
__global__ void k_scan2() {
    int u = blockIdx.x * 256 + threadIdx.x;
    int d = u & (DD - 1), cdx = (u >> 10) & 31, b = u >> 15;
    const float* base = g_L1 + (size_t)(b * TT + cdx * 64) * N1;
    float h = g_carry[(b * 32 + cdx) * DD + d];
#pragma unroll 4
    for (int t = 0; t < 64; t++) {
        float f, iv;
        gate_fi(base[(size_t)t * N1 + d], base[(size_t)t * N1 + DD + d], f, iv);
        h = fmaf(h, f, iv);
        g_H[(size_t)(b * TT + cdx * 64 + t) * DD + d] = h;
    }
}

// ---------- head-RMSNorm * gnorm * silu(g), row RMS + quant -------------------
__global__ void k_outgate(const float* __restrict__ gnw) {
    __shared__ float red[2][8];
    __shared__ float gsh[HDIM];
    int m = blockIdx.x, tid = threadIdx.x, w = tid >> 5, l = tid & 31;
    if (tid < HDIM) gsh[tid] = gnw[tid];
    __syncthreads();
    const float* hrow = g_H + (size_t)m * DD;
    const float* grow = g_L1 + (size_t)m * N1 + 2 * DD;
    float h[4], gv[4];
#pragma unroll
    for (int e = 0; e < 4; e++) {
        int n = w * 128 + e * 32 + l;
        h[e] = hrow[n]; gv[e] = grow[n];
    }
    float sA = h[0] * h[0] + h[1] * h[1];
    float sB = h[2] * h[2] + h[3] * h[3];
#pragma unroll
    for (int o = 16; o; o >>= 1) {
        sA += __shfl_xor_sync(0xffffffffu, sA, o);
        sB += __shfl_xor_sync(0xffffffffu, sB, o);
    }
    float rmsA = rsqrtf(sA * (1.f / HDIM) + GN_EPS);
    float rmsB = rsqrtf(sB * (1.f / HDIM) + GN_EPS);
    float ov[4], q2 = 0.f, am = 0.f;
#pragma unroll
    for (int e = 0; e < 4; e++) {
        int n = w * 128 + e * 32 + l;
        float r = (e < 2) ? rmsA : rmsB;
        float o = h[e] * r * gsh[n & (HDIM - 1)] * (gv[e] * sigf(gv[e]));
        ov[e] = o; q2 += o * o; am = fmaxf(am, fabsf(o));
    }
    float Q2 = bsum(q2, red[0]);
    float AM = bmax(am, red[1]);
    float rrms = rsqrtf(Q2 * (1.f / DD) + RMS_EPS);
    float clipm = fmaxf(AM * rrms, 1e-5f);
    if (tid == 0) g_rowscale[m] = clipm * (1.f / 127.f);
    float kk = rrms * 127.f / clipm;
#pragma unroll
    for (int e = 0; e < 4; e++) {
        int n = w * 128 + e * 32 + l;
        g_Aq[(size_t)m * DD + n] = __float2bfloat16(qf(ov[e] * kk));
    }
}

// --------- MLP h stats + quant (h precomputed in gate epilogue) ---------------
__global__ void k_mlpact() {
    __shared__ float red[2][8];
    int m = blockIdx.x, tid = threadIdx.x;
    const float4* row = (const float4*)(g_L3 + (size_t)m * MH);
    float4 hv[4];
    float q2 = 0.f, am = 0.f;
#pragma unroll
    for (int k = 0; k < 4; k++) {
        float4 o = row[tid + k * 256];
        hv[k] = o;
        q2 += o.x * o.x + o.y * o.y + o.z * o.z + o.w * o.w;
        am = fmaxf(am, fmaxf(fmaxf(fabsf(o.x), fabsf(o.y)), fmaxf(fabsf(o.z), fabsf(o.w))));
    }
    float Q2 = bsum(q2, red[0]);
    float AM = bmax(am, red[1]);
    float rrms = rsqrtf(Q2 * (1.f / MH) + RMS_EPS);
    float clipm = fmaxf(AM * rrms, 1e-5f);
    if (tid == 0) g_hscale[m] = clipm * (1.f / 127.f);
    float kk = rrms * 127.f / clipm;
    __nv_bfloat162* out = (__nv_bfloat162*)(g_HQ + (size_t)m * MH);
#pragma unroll
    for (int k = 0; k < 4; k++) {
        int j = tid + k * 256;
        out[j * 2]     = __floats2bfloat162_rn(qf(hv[k].x * kk), qf(hv[k].y * kk));
        out[j * 2 + 1] = __floats2bfloat162_rn(qf(hv[k].z * kk), qf(hv[k].w * kk));
    }
}

// ==== TMA-fed bf16 mma.sync GEMM, 128x256 tile, 8 warps, fused epilogues =====
__device__ __forceinline__ void mbar_init(uint32_t a, uint32_t cnt) {
    asm volatile("mbarrier.init.shared.b64 [%0], %1;" ::"r"(a), "r"(cnt) : "memory");
}
__device__ __forceinline__ void mbar_expect(uint32_t a, uint32_t tx) {
    asm volatile("mbarrier.arrive.expect_tx.shared.b64 _, [%0], %1;" ::"r"(a), "r"(tx) : "memory");
}
__device__ __forceinline__ void mbar_arrive(uint32_t a) {
    asm volatile("mbarrier.arrive.shared.b64 _, [%0];" ::"r"(a) : "memory");
}
__device__ __forceinline__ void mbar_wait(uint32_t a, uint32_t ph) {
    asm volatile(
        "{\n\t.reg .pred p;\n"
        "WL%=:\n\t"
        "mbarrier.try_wait.parity.shared::cta.b64 p, [%0], %1;\n\t"
        "@!p bra WL%=;\n\t}"
        ::"r"(a), "r"(ph) : "memory");
}
__device__ __forceinline__ void tma2d(uint32_t smem, const CUtensorMap* tm, int x, int y, uint32_t mbar) {
    asm volatile(
        "cp.async.bulk.tensor.2d.shared::cta.global.tile.mbarrier::complete_tx::bytes "
        "[%0], [%1, {%2, %3}], [%4];"
        ::"r"(smem), "l"(tm), "r"(x), "r"(y), "r"(mbar) : "memory");
}
__device__ __forceinline__ void mma16816(float* c, const uint32_t* a, const uint32_t* b) {
    asm volatile(
        "mma.sync.aligned.m16n8k16.row.col.f32.bf16.bf16.f32 "
        "{%0,%1,%2,%3}, {%4,%5,%6,%7}, {%8,%9}, {%0,%1,%2,%3};\n"
        : "+f"(c[0]), "+f"(c[1]), "+f"(c[2]), "+f"(c[3])
        : "r"(a[0]), "r"(a[1]), "r"(a[2]), "r"(a[3]), "r"(b[0]), "r"(b[1]));
}
#define LDSM4(d, addr)                                                        \
    asm volatile("ldmatrix.sync.aligned.m8n8.x4.shared.b16 {%0,%1,%2,%3}, [%4];" \
                 : "=r"((d)[0]), "=r"((d)[1]), "=r"((d)[2]), "=r"((d)[3]) : "r"(addr))
__device__ __forceinline__ uint32_t swz(int r, int kb) {
    return (uint32_t)(r * 128 + ((((kb >> 4) ^ (r & 7)) & 7) << 4) + (kb & 15));
}
#define NSG 4
#define ASTG 16384          // A: 128 rows x 128B
#define BSTG 32768          // B: 256 rows x 128B
#define STG (ASTG + BSTG)   // 49152

// resmode: 0 plain store; 1 X2=x+gmsa*v; 2 out=X2+gmlp*v; 3 h=silu(even)*odd
__global__ void __launch_bounds__(256, 1)
k_gemm(const __grid_constant__ CUtensorMap tmA, const __grid_constant__ CUtensorMap tmB,
       float* __restrict__ C, const float* __restrict__ xres, int resmode,
       int rssel, int wsbase, int nshift, int N, int K) {
    extern __shared__ __align__(1024) int8_t smd[];
    __shared__ __align__(8) uint64_t mb_full[NSG], mb_empty[NSG];
    const float* rsc = rssel ? g_hscale : g_rowscale;

    int tid = threadIdx.x;
    int bm = blockIdx.y << 7, bn = blockIdx.x << 8;
    uint32_t fb = (uint32_t)__cvta_generic_to_shared(mb_full);
    uint32_t eb = (uint32_t)__cvta_generic_to_shared(mb_empty);
    uint32_t smbase = (uint32_t)__cvta_generic_to_shared(smd);

    if (tid == 0) {
#pragma unroll
        for (int s = 0; s < NSG; s++) { mbar_init(fb + s * 8, 1); mbar_init(eb + s * 8, 8); }
    }
    __syncthreads();
    asm volatile("fence.proxy.async.shared::cta;" ::: "memory");
    __syncthreads();

    int NT = K >> 6;
    if (tid == 0) {
#pragma unroll
        for (int s = 0; s < NSG; s++) {
            mbar_expect(fb + s * 8, (uint32_t)STG);
            tma2d(smbase + s * STG, &tmA, s * 64, bm, fb + s * 8);
            tma2d(smbase + s * STG + ASTG, &tmB, s * 64, bn, fb + s * 8);
        }
    }

    int w = tid >> 5, l = tid & 31;
    int wm = (w >> 2) << 6, wn = (w & 3) << 6;   // 2x4 warp grid, 64x64 warp tile
    int g = l >> 2, tg = l & 3;
    int a_row = l & 15;
    int a_koff = (l >> 4) << 4;
    int b_row = ((l >> 4) << 3) + (l & 7);
    int b_koff = ((l >> 3) & 1) << 4;
    float acc[4][8][4] = {};

    for (int kt = 0; kt < NT; kt++) {
        int s = kt & (NSG - 1);
        uint32_t ph = (kt >> 2) & 1;
        mbar_wait(fb + s * 8, ph);
        uint32_t sA = smbase + s * STG;
        uint32_t sB = sA + ASTG;
#pragma unroll
        for (int ks = 0; ks < 4; ks++) {
            int kb = ks * 32;
            uint32_t af[4][4], bq[4][4];
#pragma unroll
            for (int mt = 0; mt < 4; mt++) {
                int r = wm + mt * 16 + a_row;
                LDSM4(af[mt], sA + swz(r, kb + a_koff));
            }
#pragma unroll
            for (int np = 0; np < 4; np++) {
                int r = wn + np * 16 + b_row;
                LDSM4(bq[np], sB + swz(r, kb + b_koff));
            }
#pragma unroll
            for (int mt = 0; mt < 4; mt++) {
#pragma unroll
                for (int np = 0; np < 4; np++) {
                    mma16816(acc[mt][np * 2],     af[mt], &bq[np][0]);
                    mma16816(acc[mt][np * 2 + 1], af[mt], &bq[np][2]);
                }
            }
        }
        if (l == 0) mbar_arrive(eb + s * 8);
        if (tid == 0 && kt + NSG < NT) {
            mbar_wait(eb + s * 8, ph);
            mbar_expect(fb + s * 8, (uint32_t)STG);
            tma2d(smbase + s * STG, &tmA, (kt + NSG) * 64, bm, fb + s * 8);
            tma2d(smbase + s * STG + ASTG, &tmB, (kt + NSG) * 64, bn, fb + s * 8);
        }
    }

    int poff = (resmode == 1) ? 2 * DD : 5 * DD;
#pragma unroll
    for (int mt = 0; mt < 4; mt++) {
        int r0 = bm + wm + mt * 16 + g;
        float s0 = rsc[r0], s1 = rsc[r0 + 8];
        int b0 = r0 >> 11, b1 = (r0 + 8) >> 11;
#pragma unroll
        for (int nt = 0; nt < 8; nt++) {
            int c0 = bn + wn + nt * 8 + tg * 2;
            float cs = g_wsinv[wsbase + (c0 >> nshift)];
            float v00 = acc[mt][nt][0] * s0 * cs, v01 = acc[mt][nt][1] * s0 * cs;
            float v10 = acc[mt][nt][2] * s1 * cs, v11 = acc[mt][nt][3] * s1 * cs;
            if (resmode == 3) {
                C[(size_t)r0 * N + (c0 >> 1)]       = siluf(v00) * v01;
                C[(size_t)(r0 + 8) * N + (c0 >> 1)] = siluf(v10) * v11;
            } else {
                if (resmode) {
                    float g00 = g_params[(size_t)b0 * 6 * DD + poff + c0];
                    float g01 = g_params[(size_t)b0 * 6 * DD + poff + c0 + 1];
                    float g10 = g_params[(size_t)b1 * 6 * DD + poff + c0];
                    float g11 = g_params[(size_t)b1 * 6 * DD + poff + c0 + 1];
                    v00 = xres[(size_t)r0 * DD + c0] + g00 * v00;
                    v01 = xres[(size_t)r0 * DD + c0 + 1] + g01 * v01;
                    v10 = xres[(size_t)(r0 + 8) * DD + c0] + g10 * v10;
                    v11 = xres[(size_t)(r0 + 8) * DD + c0 + 1] + g11 * v11;
                }
                *(float2*)(C + (size_t)r0 * N + c0) = make_float2(v00, v01);
                *(float2*)(C + (size_t)(r0 + 8) * N + c0) = make_float2(v10, v11);
            }
        }
    }
}

// ------------------------------ host ----------------------------------------
typedef CUresult (*PFN_encTM)(CUtensorMap*, CUtensorMapDataType, cuuint32_t, void*,
                              const cuuint64_t*, const cuuint64_t*, const cuuint32_t*,
                              const cuuint32_t*, CUtensorMapInterleave, CUtensorMapSwizzle,
                              CUtensorMapL2promotion, CUtensorMapFloatOOBfill);

static void make_map(PFN_encTM enc, CUtensorMap* m, void* base, uint64_t Kelems,
                     uint64_t rows, uint32_t boxrows) {
    cuuint64_t dims[2] = {Kelems, rows};
    cuuint64_t strides[1] = {Kelems * 2};
    cuuint32_t box[2] = {64, boxrows};
    cuuint32_t es[2] = {1, 1};
    enc(m, CU_TENSOR_MAP_DATA_TYPE_BFLOAT16, 2, base, dims, strides, box, es,
        CU_TENSOR_MAP_INTERLEAVE_NONE, CU_TENSOR_MAP_SWIZZLE_128B,
        CU_TENSOR_MAP_L2_PROMOTION_L2_128B, CU_TENSOR_MAP_FLOAT_OOB_FILL_NONE);
}

extern "C" void kernel_launch(void* const* d_in, const int* in_sizes, int n_in,
                              void* d_out, int out_size) {
    const float* x = (const float*)d_in[0];
    const float* c = (const float*)d_in[1];
    const float* adaln_w = (const float*)d_in[2];
    const float* adaln_b = (const float*)d_in[3];
    const float* wi = (const float*)d_in[4];
    const float* wf = (const float*)d_in[5];
    const float* wg = (const float*)d_in[6];
    const float* gnorm_w = (const float*)d_in[7];
    const float* wo = (const float*)d_in[8];
    const float* gate_w = (const float*)d_in[9];
    const float* down_w = (const float*)d_in[10];
    float* out = (float*)d_out;

    void* pf = nullptr;
    cudaDriverEntryPointQueryResult qr;
    cudaGetDriverEntryPointByVersion("cuTensorMapEncodeTiled", &pf, 12000,
                                     cudaEnableDefault, &qr);
    PFN_encTM enc = (PFN_encTM)pf;

    void *pAq, *pHQ, *pWQ, *pL1, *pL3, *pX2;
    cudaGetSymbolAddress(&pAq, g_Aq);
    cudaGetSymbolAddress(&pHQ, g_HQ);
    cudaGetSymbolAddress(&pWQ, g_WQ);
    cudaGetSymbolAddress(&pL1, g_L1);
    cudaGetSymbolAddress(&pL3, g_L3);
    cudaGetSymbolAddress(&pX2, g_X2);
    __nv_bfloat16* wq = (__nv_bfloat16*)pWQ;

    CUtensorMap mAq, mHQ, mW1, mWo, mWg, mWd;
    make_map(enc, &mAq, pAq, 1024, 8192, 128);
    make_map(enc, &mHQ, pHQ, 4096, 8192, 128);
    make_map(enc, &mW1, wq, 1024, 3072, 256);
    make_map(enc, &mWo, wq + 3145728, 1024, 1024, 256);
    make_map(enc, &mWg, wq + 4194304, 1024, 8192, 256);
    make_map(enc, &mWd, wq + 12582912, 4096, 1024, 256);

    const int GEMM_SMEM = NSG * STG;  // 196608
    cudaFuncSetAttribute(k_gemm, cudaFuncAttributeMaxDynamicSharedMemorySize, GEMM_SMEM);

    k_pre<<<3456, 256>>>(c, adaln_w, adaln_b, wi, wf, wg, wo, gate_w, down_w);
    k_lnmq<<<BT + 1, 256>>>(x, 0, DD);                     // + wfin rider
    k_quantw_all<<<16384, 256>>>(wi, wf, wg, wo, gate_w, down_w);
    // i|f|g
    k_gemm<<<dim3(12, 64), 256, GEMM_SMEM>>>(mAq, mW1, (float*)pL1, nullptr, 0, 0, 0, 10, N1, DD);
    k_scan1<<<512, 256>>>();
    k_scanc<<<16, 256>>>();
    k_scan2<<<512, 256>>>();
    k_outgate<<<BT, 256>>>(gnorm_w);
    // out proj, fused: X2 = x + gate_msa * attn
    k_gemm<<<dim3(4, 64), 256, GEMM_SMEM>>>(mAq, mWo, (float*)pX2, x, 1, 0, 3, 30, DD, DD);
    k_lnmq<<<BT, 256>>>((const float*)pX2, 3 * DD, 4 * DD);
    // gate proj (interleaved weights), fused: h = silu(gate)*y -> g_L3[BT][MH]
    k_gemm<<<dim3(32, 64), 256, GEMM_SMEM>>>(mAq, mWg, (float*)pL3, nullptr, 3, 0, 4, 30, MH, DD);
    k_mlpact<<<BT, 256>>>();
    // down proj, fused: out = X2 + gate_mlp * mlp
    k_gemm<<<dim3(4, 64), 256, GEMM_SMEM>>>(mHQ, mWd, out, (const float*)pX2, 2, 1, 5, 30, DD, MH);
}

// round 13
// speedup vs baseline: 1.0964x; 1.0964x over previous
#include <cuda_runtime.h>
#include <cuda.h>
#include <cuda_bf16.h>
#include <cstdint>

#define BB 4
#define TT 2048
#define DD 1024
#define BT 8192
#define HDIM 64
#define MH 4096
#define N1 3072
#define N3 8192
#define LN_EPS 1e-6f
#define GN_EPS 1e-5f
#define RMS_EPS 1e-8f

__device__ float g_params[BB * 6 * DD];
__device__ float g_wpart[6 * 64];
__device__ float g_wsinv[6];
__device__ __align__(1024) __nv_bfloat16 g_WQ[16 * 1024 * 1024];  // wi|wf|wg|wo|gate(interleaved)|down
__device__ __align__(1024) __nv_bfloat16 g_Aq[BT * DD];
__device__ float g_rowscale[BT];
__device__ __align__(1024) __nv_bfloat16 g_HQ[(size_t)BT * MH];
__device__ float g_hscale[BT];
__device__ float g_L1[(size_t)BT * N1];
__device__ float g_H[(size_t)BT * DD];
__device__ float g_X2[(size_t)BT * DD];
__device__ float g_L3[(size_t)BT * N3];   // h = silu(gate)*y, [BT][MH]
__device__ float g_aggA[BB * 32 * DD];
__device__ float g_aggB[BB * 32 * DD];
__device__ float g_carry[BB * 32 * DD];

__device__ __forceinline__ float sigf(float x) { return 1.f / (1.f + expf(-x)); }
__device__ __forceinline__ float siluf(float x) { return x / (1.f + expf(-x)); }

__device__ __forceinline__ float bsum(float v, float* sm) {
#pragma unroll
    for (int o = 16; o; o >>= 1) v += __shfl_xor_sync(0xffffffffu, v, o);
    if ((threadIdx.x & 31) == 0) sm[threadIdx.x >> 5] = v;
    __syncthreads();
    v = sm[threadIdx.x & 7];
#pragma unroll
    for (int o = 4; o; o >>= 1) v += __shfl_xor_sync(0xffffffffu, v, o);
    return v;
}
__device__ __forceinline__ float bmax(float v, float* sm) {
#pragma unroll
    for (int o = 16; o; o >>= 1) v = fmaxf(v, __shfl_xor_sync(0xffffffffu, v, o));
    if ((threadIdx.x & 31) == 0) sm[threadIdx.x >> 5] = v;
    __syncthreads();
    v = sm[threadIdx.x & 7];
#pragma unroll
    for (int o = 4; o; o >>= 1) v = fmaxf(v, __shfl_xor_sync(0xffffffffu, v, o));
    return v;
}
__device__ __forceinline__ float qf(float t) {
    return fminf(fmaxf(rintf(t), -128.f), 127.f);
}

// ------------- fused: adaLN (blocks 0..3071) + weight |w| sums (3072..3455) --
__global__ void k_pre(const float* __restrict__ c, const float* __restrict__ w,
                      const float* __restrict__ bias,
                      const float* w0, const float* w1, const float* w2,
                      const float* w3, const float* w4, const float* w5) {
    __shared__ float sc[DD];
    int tid = threadIdx.x;
    if (blockIdx.x < 3072) {
        int b = blockIdx.x / 768, nb = blockIdx.x % 768;
        for (int k = tid; k < DD; k += 256) { float v = c[b * DD + k]; sc[k] = v / (1.f + expf(-v)); }
        __syncthreads();
        int wid = tid >> 5, l = tid & 31;
        int n = nb * 8 + wid;
        const float4* wr = (const float4*)(w + (size_t)n * DD);
        float s = 0.f;
        for (int k4 = l; k4 < 256; k4 += 32) {
            float4 v = wr[k4];
            s += v.x * sc[k4 * 4] + v.y * sc[k4 * 4 + 1] + v.z * sc[k4 * 4 + 2] + v.w * sc[k4 * 4 + 3];
        }
#pragma unroll
        for (int o = 16; o; o >>= 1) s += __shfl_xor_sync(0xffffffffu, s, o);
        if (l == 0) g_params[b * 6 * DD + n] = s + bias[n];
    } else {
        int bid = blockIdx.x - 3072;
        int mid = bid >> 6, part = bid & 63;
        const float* ww; int n;
        switch (mid) {
            case 0: ww = w0; n = DD * DD; break;
            case 1: ww = w1; n = DD * DD; break;
            case 2: ww = w2; n = DD * DD; break;
            case 3: ww = w3; n = DD * DD; break;
            case 4: ww = w4; n = N3 * DD; break;
            default: ww = w5; n = DD * MH; break;
        }
        float s = 0.f;
        for (int i = part * 256 + tid; i < n; i += 64 * 256) s += fabsf(ww[i]);
#pragma unroll
        for (int o = 16; o; o >>= 1) s += __shfl_xor_sync(0xffffffffu, s, o);
        if ((tid & 31) == 0) sc[tid >> 5] = s;
        __syncthreads();
        if (tid == 0) {
            float t = 0.f;
            for (int i = 0; i < 8; i++) t += sc[i];
            g_wpart[bid] = t;
        }
    }
}

// ------- LN + modulate + RMS + bf16-int quant; optional rider block = wfin ---
__global__ void k_lnmq(const float* __restrict__ xin, int shift_off, int scale_off) {
    __shared__ float red[4][8];
    int m = blockIdx.x, tid = threadIdx.x;
    if (m >= BT) {
        if (tid < 6) {
            float s = 0.f;
            for (int i = 0; i < 64; i++) s += g_wpart[tid * 64 + i];
            const float cnt[6] = {1048576.f, 1048576.f, 1048576.f, 1048576.f, 8388608.f, 4194304.f};
            g_wsinv[tid] = fmaxf(s / cnt[tid], 1e-5f);
        }
        return;
    }
    int b = m >> 11;
    float4 v = ((const float4*)(xin + (size_t)m * DD))[tid];
    float S1 = bsum(v.x + v.y + v.z + v.w, red[0]);
    float mu = S1 * (1.f / DD);
    float dx = v.x - mu, dy = v.y - mu, dz = v.z - mu, dw = v.w - mu;
    float S2 = bsum(dx * dx + dy * dy + dz * dz + dw * dw, red[1]);
    float rstd = rsqrtf(S2 * (1.f / DD) + LN_EPS);
    float4 sh = ((const float4*)(g_params + (size_t)b * 6 * DD + shift_off))[tid];
    float4 sc = ((const float4*)(g_params + (size_t)b * 6 * DD + scale_off))[tid];
    float4 mo;
    mo.x = dx * rstd * (1.f + sc.x) + sh.x;
    mo.y = dy * rstd * (1.f + sc.y) + sh.y;
    mo.z = dz * rstd * (1.f + sc.z) + sh.z;
    mo.w = dw * rstd * (1.f + sc.w) + sh.w;
    float Q2 = bsum(mo.x * mo.x + mo.y * mo.y + mo.z * mo.z + mo.w * mo.w, red[2]);
    float AM = bmax(fmaxf(fmaxf(fabsf(mo.x), fabsf(mo.y)), fmaxf(fabsf(mo.z), fabsf(mo.w))), red[3]);
    float rrms = rsqrtf(Q2 * (1.f / DD) + RMS_EPS);
    float clipm = fmaxf(AM * rrms, 1e-5f);
    if (tid == 0) g_rowscale[m] = clipm * (1.f / 127.f);
    float kk = rrms * 127.f / clipm;
    __nv_bfloat162* aq = (__nv_bfloat162*)(g_Aq + (size_t)m * DD);
    aq[tid * 2]     = __floats2bfloat162_rn(qf(mo.x * kk), qf(mo.y * kk));
    aq[tid * 2 + 1] = __floats2bfloat162_rn(qf(mo.z * kk), qf(mo.w * kk));
}

// ------- fused ternary weight quant (bf16 out); gate rows interleaved --------
__global__ void k_quantw_all(const float* __restrict__ wi, const float* __restrict__ wf,
                             const float* __restrict__ wg, const float* __restrict__ wo,
                             const float* __restrict__ gw, const float* __restrict__ dw) {
    int i4 = blockIdx.x * 256 + threadIdx.x;
    const float* src; int wsid; int rel;
    if (i4 < 262144)        { src = wi; wsid = 0; rel = i4; }
    else if (i4 < 524288)   { src = wf; wsid = 1; rel = i4 - 262144; }
    else if (i4 < 786432)   { src = wg; wsid = 2; rel = i4 - 524288; }
    else if (i4 < 1048576)  { src = wo; wsid = 3; rel = i4 - 786432; }
    else if (i4 < 3145728)  { src = gw; wsid = 4; rel = i4 - 1048576; }
    else                    { src = dw; wsid = 5; rel = i4 - 3145728; }
    float ws = 1.f / g_wsinv[wsid];
    float4 v = ((const float4*)src)[rel];
    float qx = fminf(fmaxf(rintf(v.x * ws), -1.f), 1.f);
    float qy = fminf(fmaxf(rintf(v.y * ws), -1.f), 1.f);
    float qz = fminf(fmaxf(rintf(v.z * ws), -1.f), 1.f);
    float qw = fminf(fmaxf(rintf(v.w * ws), -1.f), 1.f);
    int o4 = i4;
    if (wsid == 4) {
        int lr = rel >> 8, col4 = rel & 255;
        int nr = (lr < MH) ? (lr << 1) : (((lr - MH) << 1) | 1);
        o4 = 1048576 + (nr << 8) + col4;
    }
    __nv_bfloat162* dst = (__nv_bfloat162*)g_WQ;
    dst[o4 * 2]     = __floats2bfloat162_rn(qx, qy);
    dst[o4 * 2 + 1] = __floats2bfloat162_rn(qz, qw);
}

// ---------------- chunked scan (gate transform fused) ------------------------
__device__ __forceinline__ void gate_fi(float il, float fl, float& f, float& iv) {
    f = 1.f / (1.f + expf(-fl));
    iv = (il / (1.f + expf(-il))) * (1.f - f);
}
__global__ void k_scan1() {
    int u = blockIdx.x * 256 + threadIdx.x;
    int d = u & (DD - 1), cdx = (u >> 10) & 31, b = u >> 15;
    const float* base = g_L1 + (size_t)(b * TT + cdx * 64) * N1;
    float A = 1.f, Bv = 0.f;
#pragma unroll 4
    for (int t = 0; t < 64; t++) {
        float f, iv;
        gate_fi(base[(size_t)t * N1 + d], base[(size_t)t * N1 + DD + d], f, iv);
        A *= f;
        Bv = fmaf(Bv, f, iv);
    }
    int o = (b * 32 + cdx) * DD + d;
    g_aggA[o] = A; g_aggB[o] = Bv;
}
__global__ void k_scanc() {
    int v = blockIdx.x * 256 + threadIdx.x;
    int b = v >> 10, d = v & (DD - 1);
    float carry = 0.f;
    for (int cdx = 0; cdx < 32; cdx++) {
        int o = (b * 32 + cdx) * DD + d;
        g_carry[o] = carry;
        carry = fmaf(g_aggA[o], carry, g_aggB[o]);
    }
}
__global__ void k_scan2() {
    int u = blockIdx.x * 256 + threadIdx.x;
    int d = u & (DD - 1), cdx = (u >> 10) & 31, b = u >> 15;
    const float* base = g_L1 + (size_t)(b * TT + cdx * 64) * N1;
    float h = g_carry[(b * 32 + cdx) * DD + d];
#pragma unroll 4
    for (int t = 0; t < 64; t++) {
        float f, iv;
        gate_fi(base[(size_t)t * N1 + d], base[(size_t)t * N1 + DD + d], f, iv);
        h = fmaf(h, f, iv);
        g_H[(size_t)(b * TT + cdx * 64 + t) * DD + d] = h;
    }
}

// ---------- head-RMSNorm * gnorm * silu(g), row RMS + quant -------------------
__global__ void k_outgate(const float* __restrict__ gnw) {
    __shared__ float red[2][8];
    __shared__ float gsh[HDIM];
    int m = blockIdx.x, tid = threadIdx.x, w = tid >> 5, l = tid & 31;
    if (tid < HDIM) gsh[tid] = gnw[tid];
    __syncthreads();
    const float* hrow = g_H + (size_t)m * DD;
    const float* grow = g_L1 + (size_t)m * N1 + 2 * DD;
    float h[4], gv[4];
#pragma unroll
    for (int e = 0; e < 4; e++) {
        int n = w * 128 + e * 32 + l;
        h[e] = hrow[n]; gv[e] = grow[n];
    }
    float sA = h[0] * h[0] + h[1] * h[1];
    float sB = h[2] * h[2] + h[3] * h[3];
#pragma unroll
    for (int o = 16; o; o >>= 1) {
        sA += __shfl_xor_sync(0xffffffffu, sA, o);
        sB += __shfl_xor_sync(0xffffffffu, sB, o);
    }
    float rmsA = rsqrtf(sA * (1.f / HDIM) + GN_EPS);
    float rmsB = rsqrtf(sB * (1.f / HDIM) + GN_EPS);
    float ov[4], q2 = 0.f, am = 0.f;
#pragma unroll
    for (int e = 0; e < 4; e++) {
        int n = w * 128 + e * 32 + l;
        float r = (e < 2) ? rmsA : rmsB;
        float o = h[e] * r * gsh[n & (HDIM - 1)] * (gv[e] * sigf(gv[e]));
        ov[e] = o; q2 += o * o; am = fmaxf(am, fabsf(o));
    }
    float Q2 = bsum(q2, red[0]);
    float AM = bmax(am, red[1]);
    float rrms = rsqrtf(Q2 * (1.f / DD) + RMS_EPS);
    float clipm = fmaxf(AM * rrms, 1e-5f);
    if (tid == 0) g_rowscale[m] = clipm * (1.f / 127.f);
    float kk = rrms * 127.f / clipm;
#pragma unroll
    for (int e = 0; e < 4; e++) {
        int n = w * 128 + e * 32 + l;
        g_Aq[(size_t)m * DD + n] = __float2bfloat16(qf(ov[e] * kk));
    }
}

// --------- MLP h stats + quant (h precomputed in gate epilogue) ---------------
__global__ void k_mlpact() {
    __shared__ float red[2][8];
    int m = blockIdx.x, tid = threadIdx.x;
    const float4* row = (const float4*)(g_L3 + (size_t)m * MH);
    float4 hv[4];
    float q2 = 0.f, am = 0.f;
#pragma unroll
    for (int k = 0; k < 4; k++) {
        float4 o = row[tid + k * 256];
        hv[k] = o;
        q2 += o.x * o.x + o.y * o.y + o.z * o.z + o.w * o.w;
        am = fmaxf(am, fmaxf(fmaxf(fabsf(o.x), fabsf(o.y)), fmaxf(fabsf(o.z), fabsf(o.w))));
    }
    float Q2 = bsum(q2, red[0]);
    float AM = bmax(am, red[1]);
    float rrms = rsqrtf(Q2 * (1.f / MH) + RMS_EPS);
    float clipm = fmaxf(AM * rrms, 1e-5f);
    if (tid == 0) g_hscale[m] = clipm * (1.f / 127.f);
    float kk = rrms * 127.f / clipm;
    __nv_bfloat162* out = (__nv_bfloat162*)(g_HQ + (size_t)m * MH);
#pragma unroll
    for (int k = 0; k < 4; k++) {
        int j = tid + k * 256;
        out[j * 2]     = __floats2bfloat162_rn(qf(hv[k].x * kk), qf(hv[k].y * kk));
        out[j * 2 + 1] = __floats2bfloat162_rn(qf(hv[k].z * kk), qf(hv[k].w * kk));
    }
}

// == TMA-fed bf16 mma.sync GEMM, 128x64 tile, 3 CTAs/SM (NSG=3), fused epi ===
__device__ __forceinline__ void mbar_init(uint32_t a, uint32_t cnt) {
    asm volatile("mbarrier.init.shared.b64 [%0], %1;" ::"r"(a), "r"(cnt) : "memory");
}
__device__ __forceinline__ void mbar_expect(uint32_t a, uint32_t tx) {
    asm volatile("mbarrier.arrive.expect_tx.shared.b64 _, [%0], %1;" ::"r"(a), "r"(tx) : "memory");
}
__device__ __forceinline__ void mbar_arrive(uint32_t a) {
    asm volatile("mbarrier.arrive.shared.b64 _, [%0];" ::"r"(a) : "memory");
}
__device__ __forceinline__ void mbar_wait(uint32_t a, uint32_t ph) {
    asm volatile(
        "{\n\t.reg .pred p;\n"
        "WL%=:\n\t"
        "mbarrier.try_wait.parity.shared::cta.b64 p, [%0], %1;\n\t"
        "@!p bra WL%=;\n\t}"
        ::"r"(a), "r"(ph) : "memory");
}
__device__ __forceinline__ void tma2d(uint32_t smem, const CUtensorMap* tm, int x, int y, uint32_t mbar) {
    asm volatile(
        "cp.async.bulk.tensor.2d.shared::cta.global.tile.mbarrier::complete_tx::bytes "
        "[%0], [%1, {%2, %3}], [%4];"
        ::"r"(smem), "l"(tm), "r"(x), "r"(y), "r"(mbar) : "memory");
}
__device__ __forceinline__ void mma16816(float* c, const uint32_t* a, const uint32_t* b) {
    asm volatile(
        "mma.sync.aligned.m16n8k16.row.col.f32.bf16.bf16.f32 "
        "{%0,%1,%2,%3}, {%4,%5,%6,%7}, {%8,%9}, {%0,%1,%2,%3};\n"
        : "+f"(c[0]), "+f"(c[1]), "+f"(c[2]), "+f"(c[3])
        : "r"(a[0]), "r"(a[1]), "r"(a[2]), "r"(a[3]), "r"(b[0]), "r"(b[1]));
}
#define LDSM4(d, addr)                                                        \
    asm volatile("ldmatrix.sync.aligned.m8n8.x4.shared.b16 {%0,%1,%2,%3}, [%4];" \
                 : "=r"((d)[0]), "=r"((d)[1]), "=r"((d)[2]), "=r"((d)[3]) : "r"(addr))
__device__ __forceinline__ uint32_t swz(int r, int kb) {
    return (uint32_t)(r * 128 + ((((kb >> 4) ^ (r & 7)) & 7) << 4) + (kb & 15));
}
#define NSG 3
#define ASTG 16384          // A: 128 rows x 128B
#define BSTG 8192           // B: 64 rows x 128B
#define STG (ASTG + BSTG)   // 24576

// resmode: 0 plain store; 1 X2=x+gmsa*v; 2 out=X2+gmlp*v; 3 h=silu(even)*odd
__global__ void __launch_bounds__(128, 3)
k_gemm(const __grid_constant__ CUtensorMap tmA, const __grid_constant__ CUtensorMap tmB,
       float* __restrict__ C, const float* __restrict__ xres, int resmode,
       int rssel, int wsbase, int nshift, int N, int K) {
    extern __shared__ __align__(1024) int8_t smd[];
    __shared__ __align__(8) uint64_t mb_full[NSG], mb_empty[NSG];
    const float* rsc = rssel ? g_hscale : g_rowscale;

    int tid = threadIdx.x;
    int bm = blockIdx.y << 7, bn = blockIdx.x << 6;
    uint32_t fb = (uint32_t)__cvta_generic_to_shared(mb_full);
    uint32_t eb = (uint32_t)__cvta_generic_to_shared(mb_empty);
    uint32_t smbase = (uint32_t)__cvta_generic_to_shared(smd);

    if (tid == 0) {
#pragma unroll
        for (int s = 0; s < NSG; s++) { mbar_init(fb + s * 8, 1); mbar_init(eb + s * 8, 4); }
    }
    __syncthreads();
    asm volatile("fence.proxy.async.shared::cta;" ::: "memory");
    __syncthreads();

    int NT = K >> 6;
    if (tid == 0) {
#pragma unroll
        for (int s = 0; s < NSG; s++) {
            mbar_expect(fb + s * 8, (uint32_t)STG);
            tma2d(smbase + s * STG, &tmA, s * 64, bm, fb + s * 8);
            tma2d(smbase + s * STG + ASTG, &tmB, s * 64, bn, fb + s * 8);
        }
    }

    int w = tid >> 5, l = tid & 31;
    int wm = (w >> 1) << 6, wn = (w & 1) << 5;
    int g = l >> 2, tg = l & 3;
    int a_row = l & 15;
    int a_koff = (l >> 4) << 4;
    int b_row = ((l >> 4) << 3) + (l & 7);
    int b_koff = ((l >> 3) & 1) << 4;
    float acc[4][4][4] = {};

    int s = 0, ph = 0;
    for (int kt = 0; kt < NT; kt++) {
        mbar_wait(fb + s * 8, (uint32_t)ph);
        uint32_t sA = smbase + s * STG;
        uint32_t sB = sA + ASTG;
#pragma unroll
        for (int ks = 0; ks < 4; ks++) {
            int kb = ks * 32;
            uint32_t af[4][4], bq[2][4];
#pragma unroll
            for (int mt = 0; mt < 4; mt++) {
                int r = wm + mt * 16 + a_row;
                LDSM4(af[mt], sA + swz(r, kb + a_koff));
            }
#pragma unroll
            for (int np = 0; np < 2; np++) {
                int r = wn + np * 16 + b_row;
                LDSM4(bq[np], sB + swz(r, kb + b_koff));
            }
#pragma unroll
            for (int mt = 0; mt < 4; mt++) {
#pragma unroll
                for (int np = 0; np < 2; np++) {
                    mma16816(acc[mt][np * 2],     af[mt], &bq[np][0]);
                    mma16816(acc[mt][np * 2 + 1], af[mt], &bq[np][2]);
                }
            }
        }
        if (l == 0) mbar_arrive(eb + s * 8);
        if (tid == 0 && kt + NSG < NT) {
            mbar_wait(eb + s * 8, (uint32_t)ph);
            mbar_expect(fb + s * 8, (uint32_t)STG);
            tma2d(smbase + s * STG, &tmA, (kt + NSG) * 64, bm, fb + s * 8);
            tma2d(smbase + s * STG + ASTG, &tmB, (kt + NSG) * 64, bn, fb + s * 8);
        }
        if (++s == NSG) { s = 0; ph ^= 1; }
    }

    int poff = (resmode == 1) ? 2 * DD : 5 * DD;
#pragma unroll
    for (int mt = 0; mt < 4; mt++) {
        int r0 = bm + wm + mt * 16 + g;
        float s0 = rsc[r0], s1 = rsc[r0 + 8];
        int b0 = r0 >> 11, b1 = (r0 + 8) >> 11;
#pragma unroll
        for (int nt = 0; nt < 4; nt++) {
            int c0 = bn + wn + nt * 8 + tg * 2;
            float cs = g_wsinv[wsbase + (c0 >> nshift)];
            float v00 = acc[mt][nt][0] * s0 * cs, v01 = acc[mt][nt][1] * s0 * cs;
            float v10 = acc[mt][nt][2] * s1 * cs, v11 = acc[mt][nt][3] * s1 * cs;
            if (resmode == 3) {
                C[(size_t)r0 * N + (c0 >> 1)]       = siluf(v00) * v01;
                C[(size_t)(r0 + 8) * N + (c0 >> 1)] = siluf(v10) * v11;
            } else {
                if (resmode) {
                    float g00 = g_params[(size_t)b0 * 6 * DD + poff + c0];
                    float g01 = g_params[(size_t)b0 * 6 * DD + poff + c0 + 1];
                    float g10 = g_params[(size_t)b1 * 6 * DD + poff + c0];
                    float g11 = g_params[(size_t)b1 * 6 * DD + poff + c0 + 1];
                    v00 = xres[(size_t)r0 * DD + c0] + g00 * v00;
                    v01 = xres[(size_t)r0 * DD + c0 + 1] + g01 * v01;
                    v10 = xres[(size_t)(r0 + 8) * DD + c0] + g10 * v10;
                    v11 = xres[(size_t)(r0 + 8) * DD + c0 + 1] + g11 * v11;
                }
                *(float2*)(C + (size_t)r0 * N + c0) = make_float2(v00, v01);
                *(float2*)(C + (size_t)(r0 + 8) * N + c0) = make_float2(v10, v11);
            }
        }
    }
}

// ------------------------------ host ----------------------------------------
typedef CUresult (*PFN_encTM)(CUtensorMap*, CUtensorMapDataType, cuuint32_t, void*,
                              const cuuint64_t*, const cuuint64_t*, const cuuint32_t*,
                              const cuuint32_t*, CUtensorMapInterleave, CUtensorMapSwizzle,
                              CUtensorMapL2promotion, CUtensorMapFloatOOBfill);

static void make_map(PFN_encTM enc, CUtensorMap* m, void* base, uint64_t Kelems,
                     uint64_t rows, uint32_t boxrows) {
    cuuint64_t dims[2] = {Kelems, rows};
    cuuint64_t strides[1] = {Kelems * 2};
    cuuint32_t box[2] = {64, boxrows};
    cuuint32_t es[2] = {1, 1};
    enc(m, CU_TENSOR_MAP_DATA_TYPE_BFLOAT16, 2, base, dims, strides, box, es,
        CU_TENSOR_MAP_INTERLEAVE_NONE, CU_TENSOR_MAP_SWIZZLE_128B,
        CU_TENSOR_MAP_L2_PROMOTION_L2_128B, CU_TENSOR_MAP_FLOAT_OOB_FILL_NONE);
}

extern "C" void kernel_launch(void* const* d_in, const int* in_sizes, int n_in,
                              void* d_out, int out_size) {
    const float* x = (const float*)d_in[0];
    const float* c = (const float*)d_in[1];
    const float* adaln_w = (const float*)d_in[2];
    const float* adaln_b = (const float*)d_in[3];
    const float* wi = (const float*)d_in[4];
    const float* wf = (const float*)d_in[5];
    const float* wg = (const float*)d_in[6];
    const float* gnorm_w = (const float*)d_in[7];
    const float* wo = (const float*)d_in[8];
    const float* gate_w = (const float*)d_in[9];
    const float* down_w = (const float*)d_in[10];
    float* out = (float*)d_out;

    void* pf = nullptr;
    cudaDriverEntryPointQueryResult qr;
    cudaGetDriverEntryPointByVersion("cuTensorMapEncodeTiled", &pf, 12000,
                                     cudaEnableDefault, &qr);
    PFN_encTM enc = (PFN_encTM)pf;

    void *pAq, *pHQ, *pWQ, *pL1, *pL3, *pX2;
    cudaGetSymbolAddress(&pAq, g_Aq);
    cudaGetSymbolAddress(&pHQ, g_HQ);
    cudaGetSymbolAddress(&pWQ, g_WQ);
    cudaGetSymbolAddress(&pL1, g_L1);
    cudaGetSymbolAddress(&pL3, g_L3);
    cudaGetSymbolAddress(&pX2, g_X2);
    __nv_bfloat16* wq = (__nv_bfloat16*)pWQ;

    CUtensorMap mAq, mHQ, mW1, mWo, mWg, mWd;
    make_map(enc, &mAq, pAq, 1024, 8192, 128);
    make_map(enc, &mHQ, pHQ, 4096, 8192, 128);
    make_map(enc, &mW1, wq, 1024, 3072, 64);
    make_map(enc, &mWo, wq + 3145728, 1024, 1024, 64);
    make_map(enc, &mWg, wq + 4194304, 1024, 8192, 64);
    make_map(enc, &mWd, wq + 12582912, 4096, 1024, 64);

    const int GEMM_SMEM = NSG * STG;  // 73728
    cudaFuncSetAttribute(k_gemm, cudaFuncAttributeMaxDynamicSharedMemorySize, GEMM_SMEM);

    k_pre<<<3456, 256>>>(c, adaln_w, adaln_b, wi, wf, wg, wo, gate_w, down_w);
    k_lnmq<<<BT + 1, 256>>>(x, 0, DD);                     // + wfin rider
    k_quantw_all<<<16384, 256>>>(wi, wf, wg, wo, gate_w, down_w);
    // i|f|g
    k_gemm<<<dim3(48, 64), 128, GEMM_SMEM>>>(mAq, mW1, (float*)pL1, nullptr, 0, 0, 0, 10, N1, DD);
    k_scan1<<<512, 256>>>();
    k_scanc<<<16, 256>>>();
    k_scan2<<<512, 256>>>();
    k_outgate<<<BT, 256>>>(gnorm_w);
    // out proj, fused: X2 = x + gate_msa * attn
    k_gemm<<<dim3(16, 64), 128, GEMM_SMEM>>>(mAq, mWo, (float*)pX2, x, 1, 0, 3, 30, DD, DD);
    k_lnmq<<<BT, 256>>>((const float*)pX2, 3 * DD, 4 * DD);
    // gate proj (interleaved weights), fused: h = silu(gate)*y -> g_L3[BT][MH]
    k_gemm<<<dim3(128, 64), 128, GEMM_SMEM>>>(mAq, mWg, (float*)pL3, nullptr, 3, 0, 4, 30, MH, DD);
    k_mlpact<<<BT, 256>>>();
    // down proj, fused: out = X2 + gate_mlp * mlp
    k_gemm<<<dim3(16, 64), 128, GEMM_SMEM>>>(mHQ, mWd, out, (const float*)pX2, 2, 1, 5, 30, DD, MH);
}

// round 14
// speedup vs baseline: 1.1253x; 1.0263x over previous
#include <cuda_runtime.h>
#include <cuda.h>
#include <cuda_bf16.h>
#include <cstdint>

#define BB 4
#define TT 2048
#define DD 1024
#define BT 8192
#define HDIM 64
#define MH 4096
#define N1 3072
#define N3 8192
#define LN_EPS 1e-6f
#define GN_EPS 1e-5f
#define RMS_EPS 1e-8f

__device__ float g_params[BB * 6 * DD];
__device__ float g_wpart[6 * 64];
__device__ float g_wsinv[6];
__device__ __align__(1024) __nv_bfloat16 g_WQ[16 * 1024 * 1024];  // wi|wf|wg|wo|gate(interleaved)|down
__device__ __align__(1024) __nv_bfloat16 g_Aq[BT * DD];
__device__ float g_rowscale[BT];
__device__ __align__(1024) __nv_bfloat16 g_HQ[(size_t)BT * MH];
__device__ float g_hscale[BT];
__device__ float g_L1[(size_t)BT * N1];
__device__ float g_H[(size_t)BT * DD];
__device__ float g_X2[(size_t)BT * DD];
__device__ float g_L3[(size_t)BT * N3];   // h = silu(gate)*y, [BT][MH]
__device__ float g_aggA[BB * 32 * DD];
__device__ float g_aggB[BB * 32 * DD];
__device__ float g_carry[BB * 32 * DD];

__device__ __forceinline__ float sigf(float x) { return 1.f / (1.f + expf(-x)); }
__device__ __forceinline__ float siluf(float x) { return x / (1.f + expf(-x)); }

__device__ __forceinline__ float bsum(float v, float* sm) {
#pragma unroll
    for (int o = 16; o; o >>= 1) v += __shfl_xor_sync(0xffffffffu, v, o);
    if ((threadIdx.x & 31) == 0) sm[threadIdx.x >> 5] = v;
    __syncthreads();
    v = sm[threadIdx.x & 7];
#pragma unroll
    for (int o = 4; o; o >>= 1) v += __shfl_xor_sync(0xffffffffu, v, o);
    return v;
}
__device__ __forceinline__ float bmax(float v, float* sm) {
#pragma unroll
    for (int o = 16; o; o >>= 1) v = fmaxf(v, __shfl_xor_sync(0xffffffffu, v, o));
    if ((threadIdx.x & 31) == 0) sm[threadIdx.x >> 5] = v;
    __syncthreads();
    v = sm[threadIdx.x & 7];
#pragma unroll
    for (int o = 4; o; o >>= 1) v = fmaxf(v, __shfl_xor_sync(0xffffffffu, v, o));
    return v;
}
__device__ __forceinline__ float qf(float t) {
    return fminf(fmaxf(rintf(t), -128.f), 127.f);
}

// ------------- fused: adaLN (blocks 0..3071) + weight |w| sums (3072..3455) --
__global__ void k_pre(const float* __restrict__ c, const float* __restrict__ w,
                      const float* __restrict__ bias,
                      const float* w0, const float* w1, const float* w2,
                      const float* w3, const float* w4, const float* w5) {
    __shared__ float sc[DD];
    int tid = threadIdx.x;
    if (blockIdx.x < 3072) {
        int b = blockIdx.x / 768, nb = blockIdx.x % 768;
        for (int k = tid; k < DD; k += 256) { float v = c[b * DD + k]; sc[k] = v / (1.f + expf(-v)); }
        __syncthreads();
        int wid = tid >> 5, l = tid & 31;
        int n = nb * 8 + wid;
        const float4* wr = (const float4*)(w + (size_t)n * DD);
        float s = 0.f;
        for (int k4 = l; k4 < 256; k4 += 32) {
            float4 v = wr[k4];
            s += v.x * sc[k4 * 4] + v.y * sc[k4 * 4 + 1] + v.z * sc[k4 * 4 + 2] + v.w * sc[k4 * 4 + 3];
        }
#pragma unroll
        for (int o = 16; o; o >>= 1) s += __shfl_xor_sync(0xffffffffu, s, o);
        if (l == 0) g_params[b * 6 * DD + n] = s + bias[n];
    } else {
        int bid = blockIdx.x - 3072;
        int mid = bid >> 6, part = bid & 63;
        const float* ww; int n;
        switch (mid) {
            case 0: ww = w0; n = DD * DD; break;
            case 1: ww = w1; n = DD * DD; break;
            case 2: ww = w2; n = DD * DD; break;
            case 3: ww = w3; n = DD * DD; break;
            case 4: ww = w4; n = N3 * DD; break;
            default: ww = w5; n = DD * MH; break;
        }
        float s = 0.f;
        for (int i = part * 256 + tid; i < n; i += 64 * 256) s += fabsf(ww[i]);
#pragma unroll
        for (int o = 16; o; o >>= 1) s += __shfl_xor_sync(0xffffffffu, s, o);
        if ((tid & 31) == 0) sc[tid >> 5] = s;
        __syncthreads();
        if (tid == 0) {
            float t = 0.f;
            for (int i = 0; i < 8; i++) t += sc[i];
            g_wpart[bid] = t;
        }
    }
}

// ------- LN + modulate + RMS + bf16-int quant; optional rider block = wfin ---
__global__ void k_lnmq(const float* __restrict__ xin, int shift_off, int scale_off) {
    __shared__ float red[4][8];
    int m = blockIdx.x, tid = threadIdx.x;
    if (m >= BT) {
        if (tid < 6) {
            float s = 0.f;
            for (int i = 0; i < 64; i++) s += g_wpart[tid * 64 + i];
            const float cnt[6] = {1048576.f, 1048576.f, 1048576.f, 1048576.f, 8388608.f, 4194304.f};
            g_wsinv[tid] = fmaxf(s / cnt[tid], 1e-5f);
        }
        return;
    }
    int b = m >> 11;
    float4 v = ((const float4*)(xin + (size_t)m * DD))[tid];
    float S1 = bsum(v.x + v.y + v.z + v.w, red[0]);
    float mu = S1 * (1.f / DD);
    float dx = v.x - mu, dy = v.y - mu, dz = v.z - mu, dw = v.w - mu;
    float S2 = bsum(dx * dx + dy * dy + dz * dz + dw * dw, red[1]);
    float rstd = rsqrtf(S2 * (1.f / DD) + LN_EPS);
    float4 sh = ((const float4*)(g_params + (size_t)b * 6 * DD + shift_off))[tid];
    float4 sc = ((const float4*)(g_params + (size_t)b * 6 * DD + scale_off))[tid];
    float4 mo;
    mo.x = dx * rstd * (1.f + sc.x) + sh.x;
    mo.y = dy * rstd * (1.f + sc.y) + sh.y;
    mo.z = dz * rstd * (1.f + sc.z) + sh.z;
    mo.w = dw * rstd * (1.f + sc.w) + sh.w;
    float Q2 = bsum(mo.x * mo.x + mo.y * mo.y + mo.z * mo.z + mo.w * mo.w, red[2]);
    float AM = bmax(fmaxf(fmaxf(fabsf(mo.x), fabsf(mo.y)), fmaxf(fabsf(mo.z), fabsf(mo.w))), red[3]);
    float rrms = rsqrtf(Q2 * (1.f / DD) + RMS_EPS);
    float clipm = fmaxf(AM * rrms, 1e-5f);
    if (tid == 0) g_rowscale[m] = clipm * (1.f / 127.f);
    float kk = rrms * 127.f / clipm;
    __nv_bfloat162* aq = (__nv_bfloat162*)(g_Aq + (size_t)m * DD);
    aq[tid * 2]     = __floats2bfloat162_rn(qf(mo.x * kk), qf(mo.y * kk));
    aq[tid * 2 + 1] = __floats2bfloat162_rn(qf(mo.z * kk), qf(mo.w * kk));
}

// ------- fused ternary weight quant (bf16 out); gate rows interleaved --------
__global__ void k_quantw_all(const float* __restrict__ wi, const float* __restrict__ wf,
                             const float* __restrict__ wg, const float* __restrict__ wo,
                             const float* __restrict__ gw, const float* __restrict__ dw) {
    int i4 = blockIdx.x * 256 + threadIdx.x;
    const float* src; int wsid; int rel;
    if (i4 < 262144)        { src = wi; wsid = 0; rel = i4; }
    else if (i4 < 524288)   { src = wf; wsid = 1; rel = i4 - 262144; }
    else if (i4 < 786432)   { src = wg; wsid = 2; rel = i4 - 524288; }
    else if (i4 < 1048576)  { src = wo; wsid = 3; rel = i4 - 786432; }
    else if (i4 < 3145728)  { src = gw; wsid = 4; rel = i4 - 1048576; }
    else                    { src = dw; wsid = 5; rel = i4 - 3145728; }
    float ws = 1.f / g_wsinv[wsid];
    float4 v = ((const float4*)src)[rel];
    float qx = fminf(fmaxf(rintf(v.x * ws), -1.f), 1.f);
    float qy = fminf(fmaxf(rintf(v.y * ws), -1.f), 1.f);
    float qz = fminf(fmaxf(rintf(v.z * ws), -1.f), 1.f);
    float qw = fminf(fmaxf(rintf(v.w * ws), -1.f), 1.f);
    int o4 = i4;
    if (wsid == 4) {
        int lr = rel >> 8, col4 = rel & 255;
        int nr = (lr < MH) ? (lr << 1) : (((lr - MH) << 1) | 1);
        o4 = 1048576 + (nr << 8) + col4;
    }
    __nv_bfloat162* dst = (__nv_bfloat162*)g_WQ;
    dst[o4 * 2]     = __floats2bfloat162_rn(qx, qy);
    dst[o4 * 2 + 1] = __floats2bfloat162_rn(qz, qw);
}

// ---------------- chunked scan (gate transform fused) ------------------------
__device__ __forceinline__ void gate_fi(float il, float fl, float& f, float& iv) {
    f = 1.f / (1.f + expf(-fl));
    iv = (il / (1.f + expf(-il))) * (1.f - f);
}
__global__ void k_scan1() {
    int u = blockIdx.x * 256 + threadIdx.x;
    int d = u & (DD - 1), cdx = (u >> 10) & 31, b = u >> 15;
    const float* base = g_L1 + (size_t)(b * TT + cdx * 64) * N1;
    float A = 1.f, Bv = 0.f;
#pragma unroll 4
    for (int t = 0; t < 64; t++) {
        float f, iv;
        gate_fi(base[(size_t)t * N1 + d], base[(size_t)t * N1 + DD + d], f, iv);
        A *= f;
        Bv = fmaf(Bv, f, iv);
    }
    int o = (b * 32 + cdx) * DD + d;
    g_aggA[o] = A; g_aggB[o] = Bv;
}
__global__ void k_scanc() {
    int v = blockIdx.x * 256 + threadIdx.x;
    int b = v >> 10, d = v & (DD - 1);
    float carry = 0.f;
    for (int cdx = 0; cdx < 32; cdx++) {
        int o = (b * 32 + cdx) * DD + d;
        g_carry[o] = carry;
        carry = fmaf(g_aggA[o], carry, g_aggB[o]);
    }
}
__global__ void k_scan2() {
    int u = blockIdx.x * 256 + threadIdx.x;
    int d = u & (DD - 1), cdx = (u >> 10) & 31, b = u >> 15;
    const float* base = g_L1 + (size_t)(b * TT + cdx * 64) * N1;
    float h = g_carry[(b * 32 + cdx) * DD + d];
#pragma unroll 4
    for (int t = 0; t < 64; t++) {
        float f, iv;
        gate_fi(base[(size_t)t * N1 + d], base[(size_t)t * N1 + DD + d], f, iv);
        h = fmaf(h, f, iv);
        g_H[(size_t)(b * TT + cdx * 64 + t) * DD + d] = h;
    }
}

// ---------- head-RMSNorm * gnorm * silu(g), row RMS + quant -------------------
__global__ void k_outgate(const float* __restrict__ gnw) {
    __shared__ float red[2][8];
    __shared__ float gsh[HDIM];
    int m = blockIdx.x, tid = threadIdx.x, w = tid >> 5, l = tid & 31;
    if (tid < HDIM) gsh[tid] = gnw[tid];
    __syncthreads();
    const float* hrow = g_H + (size_t)m * DD;
    const float* grow = g_L1 + (size_t)m * N1 + 2 * DD;
    float h[4], gv[4];
#pragma unroll
    for (int e = 0; e < 4; e++) {
        int n = w * 128 + e * 32 + l;
        h[e] = hrow[n]; gv[e] = grow[n];
    }
    float sA = h[0] * h[0] + h[1] * h[1];
    float sB = h[2] * h[2] + h[3] * h[3];
#pragma unroll
    for (int o = 16; o; o >>= 1) {
        sA += __shfl_xor_sync(0xffffffffu, sA, o);
        sB += __shfl_xor_sync(0xffffffffu, sB, o);
    }
    float rmsA = rsqrtf(sA * (1.f / HDIM) + GN_EPS);
    float rmsB = rsqrtf(sB * (1.f / HDIM) + GN_EPS);
    float ov[4], q2 = 0.f, am = 0.f;
#pragma unroll
    for (int e = 0; e < 4; e++) {
        int n = w * 128 + e * 32 + l;
        float r = (e < 2) ? rmsA : rmsB;
        float o = h[e] * r * gsh[n & (HDIM - 1)] * (gv[e] * sigf(gv[e]));
        ov[e] = o; q2 += o * o; am = fmaxf(am, fabsf(o));
    }
    float Q2 = bsum(q2, red[0]);
    float AM = bmax(am, red[1]);
    float rrms = rsqrtf(Q2 * (1.f / DD) + RMS_EPS);
    float clipm = fmaxf(AM * rrms, 1e-5f);
    if (tid == 0) g_rowscale[m] = clipm * (1.f / 127.f);
    float kk = rrms * 127.f / clipm;
#pragma unroll
    for (int e = 0; e < 4; e++) {
        int n = w * 128 + e * 32 + l;
        g_Aq[(size_t)m * DD + n] = __float2bfloat16(qf(ov[e] * kk));
    }
}

// --------- MLP h stats + quant (h precomputed in gate epilogue) ---------------
__global__ void k_mlpact() {
    __shared__ float red[2][8];
    int m = blockIdx.x, tid = threadIdx.x;
    const float4* row = (const float4*)(g_L3 + (size_t)m * MH);
    float4 hv[4];
    float q2 = 0.f, am = 0.f;
#pragma unroll
    for (int k = 0; k < 4; k++) {
        float4 o = row[tid + k * 256];
        hv[k] = o;
        q2 += o.x * o.x + o.y * o.y + o.z * o.z + o.w * o.w;
        am = fmaxf(am, fmaxf(fmaxf(fabsf(o.x), fabsf(o.y)), fmaxf(fabsf(o.z), fabsf(o.w))));
    }
    float Q2 = bsum(q2, red[0]);
    float AM = bmax(am, red[1]);
    float rrms = rsqrtf(Q2 * (1.f / MH) + RMS_EPS);
    float clipm = fmaxf(AM * rrms, 1e-5f);
    if (tid == 0) g_hscale[m] = clipm * (1.f / 127.f);
    float kk = rrms * 127.f / clipm;
    __nv_bfloat162* out = (__nv_bfloat162*)(g_HQ + (size_t)m * MH);
#pragma unroll
    for (int k = 0; k < 4; k++) {
        int j = tid + k * 256;
        out[j * 2]     = __floats2bfloat162_rn(qf(hv[k].x * kk), qf(hv[k].y * kk));
        out[j * 2 + 1] = __floats2bfloat162_rn(qf(hv[k].z * kk), qf(hv[k].w * kk));
    }
}

// == TMA-fed bf16 mma.sync GEMM, 128x64 tile, 4 CTAs/SM (NSG=2), templated ===
__device__ __forceinline__ void mbar_init(uint32_t a, uint32_t cnt) {
    asm volatile("mbarrier.init.shared.b64 [%0], %1;" ::"r"(a), "r"(cnt) : "memory");
}
__device__ __forceinline__ void mbar_expect(uint32_t a, uint32_t tx) {
    asm volatile("mbarrier.arrive.expect_tx.shared.b64 _, [%0], %1;" ::"r"(a), "r"(tx) : "memory");
}
__device__ __forceinline__ void mbar_arrive(uint32_t a) {
    asm volatile("mbarrier.arrive.shared.b64 _, [%0];" ::"r"(a) : "memory");
}
__device__ __forceinline__ void mbar_wait(uint32_t a, uint32_t ph) {
    asm volatile(
        "{\n\t.reg .pred p;\n"
        "WL%=:\n\t"
        "mbarrier.try_wait.parity.shared::cta.b64 p, [%0], %1;\n\t"
        "@!p bra WL%=;\n\t}"
        ::"r"(a), "r"(ph) : "memory");
}
__device__ __forceinline__ void tma2d(uint32_t smem, const CUtensorMap* tm, int x, int y, uint32_t mbar) {
    asm volatile(
        "cp.async.bulk.tensor.2d.shared::cta.global.tile.mbarrier::complete_tx::bytes "
        "[%0], [%1, {%2, %3}], [%4];"
        ::"r"(smem), "l"(tm), "r"(x), "r"(y), "r"(mbar) : "memory");
}
__device__ __forceinline__ void mma16816(float* c, const uint32_t* a, const uint32_t* b) {
    asm volatile(
        "mma.sync.aligned.m16n8k16.row.col.f32.bf16.bf16.f32 "
        "{%0,%1,%2,%3}, {%4,%5,%6,%7}, {%8,%9}, {%0,%1,%2,%3};\n"
        : "+f"(c[0]), "+f"(c[1]), "+f"(c[2]), "+f"(c[3])
        : "r"(a[0]), "r"(a[1]), "r"(a[2]), "r"(a[3]), "r"(b[0]), "r"(b[1]));
}
#define LDSM4(d, addr)                                                        \
    asm volatile("ldmatrix.sync.aligned.m8n8.x4.shared.b16 {%0,%1,%2,%3}, [%4];" \
                 : "=r"((d)[0]), "=r"((d)[1]), "=r"((d)[2]), "=r"((d)[3]) : "r"(addr))
__device__ __forceinline__ uint32_t swz(int r, int kb) {
    return (uint32_t)(r * 128 + ((((kb >> 4) ^ (r & 7)) & 7) << 4) + (kb & 15));
}
#define NSG 2
#define ASTG 16384          // A: 128 rows x 128B
#define BSTG 8192           // B: 64 rows x 128B
#define STG (ASTG + BSTG)   // 24576

// RESMODE: 0 plain store; 1 X2=x+gmsa*v; 2 out=X2+gmlp*v; 3 h=silu(even)*odd
template <int RESMODE, int RSSEL, int WSBASE, int NSHIFT, int NN, int KK>
__global__ void __launch_bounds__(128, 4)
k_gemm(const __grid_constant__ CUtensorMap tmA, const __grid_constant__ CUtensorMap tmB,
       float* __restrict__ C, const float* __restrict__ xres) {
    extern __shared__ __align__(1024) int8_t smd[];
    __shared__ __align__(8) uint64_t mb_full[NSG], mb_empty[NSG];
    const float* rsc = RSSEL ? g_hscale : g_rowscale;

    int tid = threadIdx.x;
    int bm = blockIdx.y << 7, bn = blockIdx.x << 6;
    uint32_t fb = (uint32_t)__cvta_generic_to_shared(mb_full);
    uint32_t eb = (uint32_t)__cvta_generic_to_shared(mb_empty);
    uint32_t smbase = (uint32_t)__cvta_generic_to_shared(smd);

    if (tid == 0) {
#pragma unroll
        for (int s = 0; s < NSG; s++) { mbar_init(fb + s * 8, 1); mbar_init(eb + s * 8, 4); }
    }
    __syncthreads();
    asm volatile("fence.proxy.async.shared::cta;" ::: "memory");
    __syncthreads();

    constexpr int NT = KK >> 6;
    if (tid == 0) {
#pragma unroll
        for (int s = 0; s < NSG; s++) {
            mbar_expect(fb + s * 8, (uint32_t)STG);
            tma2d(smbase + s * STG, &tmA, s * 64, bm, fb + s * 8);
            tma2d(smbase + s * STG + ASTG, &tmB, s * 64, bn, fb + s * 8);
        }
    }

    int w = tid >> 5, l = tid & 31;
    int wm = (w >> 1) << 6, wn = (w & 1) << 5;
    int g = l >> 2, tg = l & 3;
    int a_row = l & 15;
    int a_koff = (l >> 4) << 4;
    int b_row = ((l >> 4) << 3) + (l & 7);
    int b_koff = ((l >> 3) & 1) << 4;
    float acc[4][4][4] = {};

    int s = 0, ph = 0;
    for (int kt = 0; kt < NT; kt++) {
        mbar_wait(fb + s * 8, (uint32_t)ph);
        uint32_t sA = smbase + s * STG;
        uint32_t sB = sA + ASTG;
#pragma unroll
        for (int ks = 0; ks < 4; ks++) {
            int kb = ks * 32;
            uint32_t af[4][4], bq[2][4];
#pragma unroll
            for (int mt = 0; mt < 4; mt++) {
                int r = wm + mt * 16 + a_row;
                LDSM4(af[mt], sA + swz(r, kb + a_koff));
            }
#pragma unroll
            for (int np = 0; np < 2; np++) {
                int r = wn + np * 16 + b_row;
                LDSM4(bq[np], sB + swz(r, kb + b_koff));
            }
#pragma unroll
            for (int mt = 0; mt < 4; mt++) {
#pragma unroll
                for (int np = 0; np < 2; np++) {
                    mma16816(acc[mt][np * 2],     af[mt], &bq[np][0]);
                    mma16816(acc[mt][np * 2 + 1], af[mt], &bq[np][2]);
                }
            }
        }
        if (l == 0) mbar_arrive(eb + s * 8);
        if (tid == 0 && kt + NSG < NT) {
            mbar_wait(eb + s * 8, (uint32_t)ph);
            mbar_expect(fb + s * 8, (uint32_t)STG);
            tma2d(smbase + s * STG, &tmA, (kt + NSG) * 64, bm, fb + s * 8);
            tma2d(smbase + s * STG + ASTG, &tmB, (kt + NSG) * 64, bn, fb + s * 8);
        }
        if (++s == NSG) { s = 0; ph ^= 1; }
    }

    constexpr int POFF = (RESMODE == 1) ? 2 * DD : 5 * DD;
#pragma unroll
    for (int mt = 0; mt < 4; mt++) {
        int r0 = bm + wm + mt * 16 + g;
        float s0 = rsc[r0], s1 = rsc[r0 + 8];
        int b0 = r0 >> 11, b1 = (r0 + 8) >> 11;
#pragma unroll
        for (int nt = 0; nt < 4; nt++) {
            int c0 = bn + wn + nt * 8 + tg * 2;
            float cs = g_wsinv[WSBASE + (c0 >> NSHIFT)];
            float v00 = acc[mt][nt][0] * s0 * cs, v01 = acc[mt][nt][1] * s0 * cs;
            float v10 = acc[mt][nt][2] * s1 * cs, v11 = acc[mt][nt][3] * s1 * cs;
            if (RESMODE == 3) {
                C[(size_t)r0 * NN + (c0 >> 1)]       = siluf(v00) * v01;
                C[(size_t)(r0 + 8) * NN + (c0 >> 1)] = siluf(v10) * v11;
            } else {
                if (RESMODE == 1 || RESMODE == 2) {
                    float g00 = g_params[(size_t)b0 * 6 * DD + POFF + c0];
                    float g01 = g_params[(size_t)b0 * 6 * DD + POFF + c0 + 1];
                    float g10 = g_params[(size_t)b1 * 6 * DD + POFF + c0];
                    float g11 = g_params[(size_t)b1 * 6 * DD + POFF + c0 + 1];
                    v00 = xres[(size_t)r0 * DD + c0] + g00 * v00;
                    v01 = xres[(size_t)r0 * DD + c0 + 1] + g01 * v01;
                    v10 = xres[(size_t)(r0 + 8) * DD + c0] + g10 * v10;
                    v11 = xres[(size_t)(r0 + 8) * DD + c0 + 1] + g11 * v11;
                }
                *(float2*)(C + (size_t)r0 * NN + c0) = make_float2(v00, v01);
                *(float2*)(C + (size_t)(r0 + 8) * NN + c0) = make_float2(v10, v11);
            }
        }
    }
}

// ------------------------------ host ----------------------------------------
typedef CUresult (*PFN_encTM)(CUtensorMap*, CUtensorMapDataType, cuuint32_t, void*,
                              const cuuint64_t*, const cuuint64_t*, const cuuint32_t*,
                              const cuuint32_t*, CUtensorMapInterleave, CUtensorMapSwizzle,
                              CUtensorMapL2promotion, CUtensorMapFloatOOBfill);

static void make_map(PFN_encTM enc, CUtensorMap* m, void* base, uint64_t Kelems,
                     uint64_t rows, uint32_t boxrows) {
    cuuint64_t dims[2] = {Kelems, rows};
    cuuint64_t strides[1] = {Kelems * 2};
    cuuint32_t box[2] = {64, boxrows};
    cuuint32_t es[2] = {1, 1};
    enc(m, CU_TENSOR_MAP_DATA_TYPE_BFLOAT16, 2, base, dims, strides, box, es,
        CU_TENSOR_MAP_INTERLEAVE_NONE, CU_TENSOR_MAP_SWIZZLE_128B,
        CU_TENSOR_MAP_L2_PROMOTION_L2_128B, CU_TENSOR_MAP_FLOAT_OOB_FILL_NONE);
}

extern "C" void kernel_launch(void* const* d_in, const int* in_sizes, int n_in,
                              void* d_out, int out_size) {
    const float* x = (const float*)d_in[0];
    const float* c = (const float*)d_in[1];
    const float* adaln_w = (const float*)d_in[2];
    const float* adaln_b = (const float*)d_in[3];
    const float* wi = (const float*)d_in[4];
    const float* wf = (const float*)d_in[5];
    const float* wg = (const float*)d_in[6];
    const float* gnorm_w = (const float*)d_in[7];
    const float* wo = (const float*)d_in[8];
    const float* gate_w = (const float*)d_in[9];
    const float* down_w = (const float*)d_in[10];
    float* out = (float*)d_out;

    void* pf = nullptr;
    cudaDriverEntryPointQueryResult qr;
    cudaGetDriverEntryPointByVersion("cuTensorMapEncodeTiled", &pf, 12000,
                                     cudaEnableDefault, &qr);
    PFN_encTM enc = (PFN_encTM)pf;

    void *pAq, *pHQ, *pWQ, *pL1, *pL3, *pX2;
    cudaGetSymbolAddress(&pAq, g_Aq);
    cudaGetSymbolAddress(&pHQ, g_HQ);
    cudaGetSymbolAddress(&pWQ, g_WQ);
    cudaGetSymbolAddress(&pL1, g_L1);
    cudaGetSymbolAddress(&pL3, g_L3);
    cudaGetSymbolAddress(&pX2, g_X2);
    __nv_bfloat16* wq = (__nv_bfloat16*)pWQ;

    CUtensorMap mAq, mHQ, mW1, mWo, mWg, mWd;
    make_map(enc, &mAq, pAq, 1024, 8192, 128);
    make_map(enc, &mHQ, pHQ, 4096, 8192, 128);
    make_map(enc, &mW1, wq, 1024, 3072, 64);
    make_map(enc, &mWo, wq + 3145728, 1024, 1024, 64);
    make_map(enc, &mWg, wq + 4194304, 1024, 8192, 64);
    make_map(enc, &mWd, wq + 12582912, 4096, 1024, 64);

    const int GEMM_SMEM = NSG * STG;  // 49152
    cudaFuncSetAttribute(k_gemm<0, 0, 0, 10, N1, DD>, cudaFuncAttributeMaxDynamicSharedMemorySize, GEMM_SMEM);
    cudaFuncSetAttribute(k_gemm<1, 0, 3, 30, DD, DD>, cudaFuncAttributeMaxDynamicSharedMemorySize, GEMM_SMEM);
    cudaFuncSetAttribute(k_gemm<3, 0, 4, 30, MH, DD>, cudaFuncAttributeMaxDynamicSharedMemorySize, GEMM_SMEM);
    cudaFuncSetAttribute(k_gemm<2, 1, 5, 30, DD, MH>, cudaFuncAttributeMaxDynamicSharedMemorySize, GEMM_SMEM);

    k_pre<<<3456, 256>>>(c, adaln_w, adaln_b, wi, wf, wg, wo, gate_w, down_w);
    k_lnmq<<<BT + 1, 256>>>(x, 0, DD);                     // + wfin rider
    k_quantw_all<<<16384, 256>>>(wi, wf, wg, wo, gate_w, down_w);
    // i|f|g
    k_gemm<0, 0, 0, 10, N1, DD><<<dim3(48, 64), 128, GEMM_SMEM>>>(mAq, mW1, (float*)pL1, nullptr);
    k_scan1<<<512, 256>>>();
    k_scanc<<<16, 256>>>();
    k_scan2<<<512, 256>>>();
    k_outgate<<<BT, 256>>>(gnorm_w);
    // out proj, fused: X2 = x + gate_msa * attn
    k_gemm<1, 0, 3, 30, DD, DD><<<dim3(16, 64), 128, GEMM_SMEM>>>(mAq, mWo, (float*)pX2, x);
    k_lnmq<<<BT, 256>>>((const float*)pX2, 3 * DD, 4 * DD);
    // gate proj (interleaved weights), fused: h = silu(gate)*y -> g_L3[BT][MH]
    k_gemm<3, 0, 4, 30, MH, DD><<<dim3(128, 64), 128, GEMM_SMEM>>>(mAq, mWg, (float*)pL3, nullptr);
    k_mlpact<<<BT, 256>>>();
    // down proj, fused: out = X2 + gate_mlp * mlp
    k_gemm<2, 1, 5, 30, DD, MH><<<dim3(16, 64), 128, GEMM_SMEM>>>(mHQ, mWd, out, (const float*)pX2);
}